// round 16
// baseline (speedup 1.0000x reference)
#include <cuda_runtime.h>

typedef unsigned long long u64;
typedef unsigned int u32;

#define BATCH 16
#define NPRI  3000
#define NCLS  201
#define CM1   200
#define NCAND (NPRI * CM1)
#define TOPN  100
#define SCORE_THRESH 0.02f
#define NMS_THRESH   0.45f
#define BKTG  256           /* global per-label bucket capacity */
#define SBK   32            /* post-B-filter per-label capacity */
#define CCAP  4096          /* emitted-pick capacity            */
#define NSLC  8             /* label slices per image           */
#define LPS   25            /* labels per slice (8*25=200)      */

/* ---- static device scratch (zero-init at load; rank restores zeros) ---- */
__device__ u64    g_bkt[(long)BATCH * 256 * BKTG];   /* per-(image,label) keys */
__device__ int    g_bcnt[BATCH * 256];
__device__ u64    g_spill[(long)BATCH * NCAND];      /* bucket-overflow spill  */
__device__ int    g_spillcnt[BATCH];
__device__ u64    g_lmax[BATCH * 256];               /* per-(image,label) max  */
__device__ u64    g_comp[BATCH * CCAP];              /* emitted picks          */
__device__ int    g_ccnt[BATCH];
__device__ int    g_seq[BATCH];                      /* force-seq flag         */
__device__ u32    g_maxbits[BATCH];                  /* max fenc(coord)        */
__device__ u32    g_minbits[BATCH];                  /* max fenc(-coord)=>min  */
__device__ float4 g_decoded[BATCH * NPRI];

__device__ __forceinline__ u64 umax64(u64 a, u64 b) { return a > b ? a : b; }

__device__ __forceinline__ unsigned fenc(float f) {
    unsigned u = __float_as_uint(f);
    return (u & 0x80000000u) ? ~u : (u | 0x80000000u);
}
__device__ __forceinline__ float fdec(unsigned e) {
    unsigned u = (e & 0x80000000u) ? (e & 0x7fffffffu) : ~e;
    return __uint_as_float(u);
}

__device__ __forceinline__ u64 wmax64(u64 k) {
    u32 hi = (u32)(k >> 32);
    u32 mh = __reduce_max_sync(0xffffffffu, hi);
    u32 ml = __reduce_max_sync(0xffffffffu, (hi == mh) ? (u32)k : 0u);
    return ((u64)mh << 32) | ml;
}

/* score (positive float bits) -> 256-bin monotone bucket over (0.02, 1.0] */
__device__ __forceinline__ int score_bin(u32 khi) {
    int v = (int)(khi >> 18) - 3880;
    return v < 0 ? 0 : (v > 255 ? 255 : v);
}

/* grid (NPRI/8, BATCH), block 256: one warp per (image, prior) row */
__global__ void stage_a(const float* __restrict__ deltas,
                        const float* __restrict__ obj,
                        const float* __restrict__ priors) {
    const int lane = threadIdx.x & 31;
    const int wid  = threadIdx.x >> 5;
    const int p    = blockIdx.x * 8 + wid;
    const int b    = blockIdx.y;
    const long row = (long)b * NPRI + p;
    const float* o = obj + row * NCLS;

    /* softmax over 201 classes (arithmetic identical to prior rounds) */
    float v[7];
    float m = -3.4e38f;
#pragma unroll
    for (int k = 0; k < 7; k++) {
        int c = lane + 32 * k;
        v[k] = (c < NCLS) ? o[c] : -3.4e38f;
        m = fmaxf(m, v[k]);
    }
#pragma unroll
    for (int d = 16; d; d >>= 1) m = fmaxf(m, __shfl_xor_sync(0xffffffffu, m, d));
    float e[7]; float sum = 0.f;
#pragma unroll
    for (int k = 0; k < 7; k++) {
        int c = lane + 32 * k;
        e[k] = (c < NCLS) ? expf(v[k] - m) : 0.f;
        sum += e[k];
    }
#pragma unroll
    for (int d = 16; d; d >>= 1) sum += __shfl_xor_sync(0xffffffffu, sum, d);

    /* prefilter (no false negatives), exact divide only for ~3% of elems;
       passing candidates go straight into per-(image,label) global buckets */
    const float pre = 0.0195f * sum;
#pragma unroll
    for (int k = 0; k < 7; k++) {
        int c = lane + 32 * k;
        if (c >= 1 && c < NCLS && e[k] > pre) {
            float pv = __fdiv_rn(e[k], sum);
            if (pv > SCORE_THRESH) {
                int labf = c - 1;
                u32 pk = ((u32)p << 8) | (u32)labf;
                u64 key = ((u64)__float_as_uint(pv) << 32) | (u32)(~pk);
                atomicMax(&g_lmax[b * 256 + labf], key);
                int pos = atomicAdd(&g_bcnt[b * 256 + labf], 1);
                if (pos < BKTG)
                    g_bkt[((long)b * 256 + labf) * BKTG + pos] = key;
                else {
                    int sp = atomicAdd(&g_spillcnt[b], 1);
                    g_spill[(long)b * NCAND + sp] = key;
                }
            }
        }
    }

    if (lane == 0) {
        float4 dl = ((const float4*)deltas)[row];
        float4 pr = ((const float4*)priors)[p];
        float pw = pr.z, ph = pr.w;
        float cx = dl.x * 0.1f * pw + pr.x;
        float cy = dl.y * 0.1f * ph + pr.y;
        float bw = expf(dl.z * 0.2f) * pw;
        float bh = expf(dl.w * 0.2f) * ph;
        float x1 = cx - 0.5f * bw, y1 = cy - 0.5f * bh;
        float x2 = cx + 0.5f * bw, y2 = cy + 0.5f * bh;
        g_decoded[row] = make_float4(x1, y1, x2, y2);
        float mm = fmaxf(fmaxf(x1, y1), fmaxf(x2, y2));
        float mn = fminf(fminf(x1, y1), fminf(x2, y2));
        atomicMax(&g_maxbits[b], fenc(mm));
        atomicMax(&g_minbits[b], fenc(-mn));
    }
}

/* grid (NSLC, BATCH), 256 threads: per-slice filter + per-label NMS */
__global__ void __launch_bounds__(256) nms_a() {
    __shared__ int hist[256];
    __shared__ int misc[4];          /* 0:B 1:nlab */
    __shared__ u64 sb[LPS][SBK];
    __shared__ int sbc[LPS];
    __shared__ int ovf;

    const int b   = blockIdx.y;
    const int s   = blockIdx.x;
    const int tid = threadIdx.x;
    const int wid = tid >> 5, lane = tid & 31;

    const float minv = -fdec(g_minbits[b]);
    if (minv <= -1.0f) return;                         /* rank takes seq */
    if (g_spillcnt[b] > 0) {                           /* overflow: seq  */
        if (tid == 0 && s == 0) g_seq[b] = 1;
        return;
    }
    const float off = fdec(g_maxbits[b]) + 1.0f;

    if (tid < 256) hist[tid] = 0;
    if (tid < 4)   misc[tid] = 0;
    if (tid < LPS) sbc[tid] = 0;
    if (tid == 0)  ovf = 0;
    __syncthreads();

    /* histogram of per-label maxes (all 200, read-only) */
    if (tid < CM1) {
        u64 lm = g_lmax[b * 256 + tid];
        if (lm) {
            atomicAdd(&hist[score_bin((u32)(lm >> 32))], 1);
            atomicAdd(&misc[1], 1);
        }
    }
    __syncthreads();

    /* threshold bin B: smallest suffix of label-max bins with count >= TOPN */
    if (wid == 0) {
        int nlab = misc[1];
        if (nlab < TOPN) {
            if (lane == 0) misc[0] = 0;
        } else {
            int carry = 0; bool found = false;
            for (int r = 0; r < 8 && !found; r++) {
                int bin = 255 - (r * 32 + lane);
                int c = hist[bin];
                int vv = c;
#pragma unroll
                for (int d = 1; d < 32; d <<= 1) {
                    int t = __shfl_up_sync(0xffffffffu, vv, d);
                    if (lane >= d) vv += t;
                }
                int cum = carry + vv;
                unsigned ball = __ballot_sync(0xffffffffu, cum >= TOPN);
                if (ball) {
                    int ff = __ffs(ball) - 1;
                    if (lane == ff) misc[0] = bin;
                    found = true;
                }
                carry += __shfl_sync(0xffffffffu, vv, 31);
            }
            if (!found && lane == 0) misc[0] = 0;
        }
    }
    __syncthreads();
    const int B = misc[0];

    /* filtered gather: warp w handles local labels w, w+8, w+16, w+24 */
    for (int ll = wid; ll < LPS; ll += 8) {
        int l = s * LPS + ll;
        int c = g_bcnt[b * 256 + l];                   /* <= BKTG (no spill) */
        const u64* gb = g_bkt + ((long)b * 256 + l) * BKTG;
        for (int j = lane; j < c; j += 32) {
            u64 k = gb[j];
            if (score_bin((u32)(k >> 32)) >= B) {
                int pos = atomicAdd(&sbc[ll], 1);
                if (pos < SBK) sb[ll][pos] = k;
                else ovf = 1;
            }
        }
    }
    __syncthreads();
    if (ovf) { if (tid == 0) g_seq[b] = 1; return; }

    /* per-label greedy NMS, one thread per label (tiny segments) */
    if (tid < LPS) {
        int c = sbc[tid];
        if (c > 0) {
            int l = s * LPS + tid;
            u64* seg = sb[tid];
            float shift = __fmul_rn((float)(l + 1), off);
            const float4* dec = g_decoded + (long)b * NPRI;
            for (int pick = 0; pick < TOPN; pick++) {
                u64 best = 0;
                for (int j = 0; j < c; j++) best = umax64(best, seg[j]);
                if (!best) break;
                int pos = atomicAdd(&g_ccnt[b], 1);
                if (pos < CCAP) g_comp[b * CCAP + pos] = best;
                else g_seq[b] = 1;
                float4 d4 = dec[(int)((~(u32)best) >> 8)];
                float px1 = __fadd_rn(d4.x, shift), py1 = __fadd_rn(d4.y, shift);
                float px2 = __fadd_rn(d4.z, shift), py2 = __fadd_rn(d4.w, shift);
                float pare = __fmul_rn(__fsub_rn(px2, px1), __fsub_rn(py2, py1));
                for (int j = 0; j < c; j++) {
                    u64 k = seg[j];
                    if (!k) continue;
                    if (k == best) { seg[j] = 0ULL; continue; }
                    float4 c4 = dec[(int)((~(u32)k) >> 8)];
                    float x1 = __fadd_rn(c4.x, shift), y1 = __fadd_rn(c4.y, shift);
                    float x2 = __fadd_rn(c4.z, shift), y2 = __fadd_rn(c4.w, shift);
                    float ix1 = fmaxf(x1, px1), iy1 = fmaxf(y1, py1);
                    float ix2 = fminf(x2, px2), iy2 = fminf(y2, py2);
                    float inter = __fmul_rn(fmaxf(__fsub_rn(ix2, ix1), 0.f),
                                            fmaxf(__fsub_rn(iy2, iy1), 0.f));
                    float ar  = __fmul_rn(__fsub_rn(x2, x1), __fsub_rn(y2, y1));
                    float iou = __fdiv_rn(inter, __fsub_rn(__fadd_rn(ar, pare), inter));
                    if (iou > NMS_THRESH) seg[j] = 0ULL;
                }
            }
        }
    }
}

/* grid BATCH, 1024 threads: rank picks, write output, reset state */
__global__ void __launch_bounds__(1024) rank_kernel(float* __restrict__ out) {
    __shared__ u64 sc[CCAP];
    __shared__ u64 red[32];
    __shared__ float fbc[8];
    __shared__ int scnt[256];

    const int b   = blockIdx.x;
    const int tid = threadIdx.x;
    const int wid = tid >> 5, lane = tid & 31;

    const float minv = -fdec(g_minbits[b]);
    const float off  = fdec(g_maxbits[b]) + 1.0f;
    const bool  seq  = (minv <= -1.0f) || (g_seq[b] != 0) || (g_ccnt[b] > CCAP);
    const float4* dec = g_decoded + (long)b * NPRI;

    for (int q = tid; q < TOPN * 6; q += 1024) out[(long)b * TOPN * 6 + q] = 0.f;

    if (!seq) {
        const int M = g_ccnt[b];
        for (int i = tid; i < M; i += 1024) sc[i] = g_comp[b * CCAP + i];
        __syncthreads();
        /* exact rank-by-count (keys unique): row = #keys greater */
        for (int i = tid; i < M; i += 1024) {
            u64 k = sc[i];
            int r = 0;
            for (int j = 0; j < M; j++) r += (sc[j] > k);
            if (r < TOPN) {
                u32 pk = ~(u32)k;
                int pr = (int)(pk >> 8), labf = (int)(pk & 255u);
                float4 d4 = dec[pr];
                float* orow = out + ((long)b * TOPN + r) * 6;
                orow[0] = fminf(fmaxf(d4.x, 0.f), 1.f);
                orow[1] = fminf(fmaxf(d4.y, 0.f), 1.f);
                orow[2] = fminf(fmaxf(d4.z, 0.f), 1.f);
                orow[3] = fminf(fmaxf(d4.w, 0.f), 1.f);
                orow[4] = __uint_as_float((u32)(k >> 32));
                orow[5] = (float)(labf + 1);
            }
        }
    } else {
        /* exact sequential fallback over buckets + spill */
        if (tid < 256) scnt[tid] = (g_bcnt[b * 256 + tid] < BKTG)
                                   ? g_bcnt[b * 256 + tid] : BKTG;
        __syncthreads();
        u64* base = g_bkt + (long)b * 256 * BKTG;
        u64* spl  = g_spill + (long)b * NCAND;
        const int sp = g_spillcnt[b];
        __syncthreads();
        for (int it = 0; it < TOPN; it++) {
            u64 bk = 0;
            for (int j = tid; j < 256 * BKTG; j += 1024) {
                if ((j & (BKTG - 1)) < scnt[j >> 8]) bk = umax64(bk, base[j]);
            }
            for (int j = tid; j < sp; j += 1024) bk = umax64(bk, spl[j]);
            bk = wmax64(bk);
            if (lane == 0) red[wid] = bk;
            __syncthreads();
            if (tid == 0) {
                for (int k = 1; k < 32; k++) bk = umax64(bk, red[k]);
                red[0] = bk;
                if (bk != 0ULL) {
                    u32 pk = ~(u32)bk;
                    int pr = (int)(pk >> 8), labf = (int)(pk & 255u);
                    float4 d4 = dec[pr];
                    float shift = __fmul_rn((float)(labf + 1), off);
                    float px1 = __fadd_rn(d4.x, shift), py1 = __fadd_rn(d4.y, shift);
                    float px2 = __fadd_rn(d4.z, shift), py2 = __fadd_rn(d4.w, shift);
                    fbc[0] = px1; fbc[1] = py1; fbc[2] = px2; fbc[3] = py2;
                    fbc[4] = __fmul_rn(__fsub_rn(px2, px1), __fsub_rn(py2, py1));
                    float* orow = out + ((long)b * TOPN + it) * 6;
                    orow[0] = fminf(fmaxf(d4.x, 0.f), 1.f);
                    orow[1] = fminf(fmaxf(d4.y, 0.f), 1.f);
                    orow[2] = fminf(fmaxf(d4.z, 0.f), 1.f);
                    orow[3] = fminf(fmaxf(d4.w, 0.f), 1.f);
                    orow[4] = __uint_as_float((u32)(bk >> 32));
                    orow[5] = (float)(labf + 1);
                }
            }
            __syncthreads();
            u64 pick = red[0];
            if (pick == 0ULL) break;
            float px1 = fbc[0], py1 = fbc[1];
            float px2 = fbc[2], py2 = fbc[3], pare = fbc[4];
            for (int j = tid; j < 256 * BKTG + sp; j += 1024) {
                u64 k; u64* slot;
                if (j < 256 * BKTG) {
                    if ((j & (BKTG - 1)) >= scnt[j >> 8]) continue;
                    slot = base + j;
                } else {
                    slot = spl + (j - 256 * BKTG);
                }
                k = *slot;
                if (!k) continue;
                if (k == pick) { *slot = 0ULL; continue; }
                u32 pk2 = ~(u32)k;
                float4 c4 = dec[pk2 >> 8];
                float shift2 = __fmul_rn((float)((pk2 & 255u) + 1), off);
                float x1 = __fadd_rn(c4.x, shift2), y1 = __fadd_rn(c4.y, shift2);
                float x2 = __fadd_rn(c4.z, shift2), y2 = __fadd_rn(c4.w, shift2);
                float ix1 = fmaxf(x1, px1), iy1 = fmaxf(y1, py1);
                float ix2 = fminf(x2, px2), iy2 = fminf(y2, py2);
                float inter = __fmul_rn(fmaxf(__fsub_rn(ix2, ix1), 0.f),
                                        fmaxf(__fsub_rn(iy2, iy1), 0.f));
                float ar  = __fmul_rn(__fsub_rn(x2, x1), __fsub_rn(y2, y1));
                float iou = __fdiv_rn(inter, __fsub_rn(__fadd_rn(ar, pare), inter));
                if (iou > NMS_THRESH) *slot = 0ULL;
            }
            __syncthreads();
        }
    }

    /* reset all per-image state for the next graph replay */
    __syncthreads();
    if (tid < 256) { g_bcnt[b * 256 + tid] = 0; g_lmax[b * 256 + tid] = 0ULL; }
    if (tid == 0) {
        g_ccnt[b] = 0; g_spillcnt[b] = 0; g_seq[b] = 0;
        g_maxbits[b] = 0u; g_minbits[b] = 0u;
    }
}

extern "C" void kernel_launch(void* const* d_in, const int* in_sizes, int n_in,
                              void* d_out, int out_size) {
    const float *deltas = nullptr, *obj = nullptr, *priors = nullptr;
    for (int i = 0; i < n_in; i++) {
        if      (in_sizes[i] == BATCH * NPRI * 4)    deltas = (const float*)d_in[i];
        else if (in_sizes[i] == BATCH * NPRI * NCLS) obj    = (const float*)d_in[i];
        else if (in_sizes[i] == NPRI * 4)            priors = (const float*)d_in[i];
    }
    dim3 g(NPRI / 8, BATCH);
    stage_a<<<g, 256>>>(deltas, obj, priors);
    dim3 g2(NSLC, BATCH);
    nms_a<<<g2, 256>>>();
    rank_kernel<<<BATCH, 1024>>>((float*)d_out);
}